// round 14
// baseline (speedup 1.0000x reference)
#include <cuda_runtime.h>

#define NGRAPH 64
#define SPTS   1024
#define TILE   128
#define NTILE  8
#define NPAIRS 36           // tile-pairs per graph (ti <= tj)
#define HIDDEN 256
#define NBINS  64
#define HROWS  66           // 64 bins + dump row + 1 pad row (uint4 init)
#define SLICE  32           // output units per mlp block

typedef unsigned long long ull;

// per-(graph, tile-pair-block) partial histograms; fully overwritten every call
__device__ unsigned int g_part[NGRAPH][NPAIRS][NBINS];

// ---------- helpers ----------
__device__ __forceinline__ unsigned smem_u32(const void* p) {
    unsigned a;
    asm("{ .reg .u64 t; cvta.to.shared.u64 t, %1; cvt.u32.u64 %0, t; }" : "=r"(a) : "l"(p));
    return a;
}
__device__ __forceinline__ ull f2_pack(float a, float b) {
    ull r; asm("mov.b64 %0, {%1, %2};" : "=l"(r) : "f"(a), "f"(b)); return r;
}
__device__ __forceinline__ void f2_unpack(ull v, float& a, float& b) {
    asm("mov.b64 {%0, %1}, %2;" : "=f"(a), "=f"(b) : "l"(v));
}
__device__ __forceinline__ ull f2_add(ull a, ull b) {
    ull r; asm("add.rn.f32x2 %0, %1, %2;" : "=l"(r) : "l"(a), "l"(b)); return r;
}
__device__ __forceinline__ ull f2_mul(ull a, ull b) {
    ull r; asm("mul.rn.f32x2 %0, %1, %2;" : "=l"(r) : "l"(a), "l"(b)); return r;
}
__device__ __forceinline__ ull f2_fma(ull a, ull b, ull c) {
    ull r; asm("fma.rn.f32x2 %0, %1, %2, %3;" : "=l"(r) : "l"(a), "l"(b), "l"(c)); return r;
}
__device__ __forceinline__ float fsqrt_approx(float x) {
    float y; asm("sqrt.approx.f32 %0, %1;" : "=f"(y) : "f"(x)); return y;
}

// byte offset of the bin row for scaled squared distance d2.
// v = bits(fmin(sqrt(d2),64) + (2^23-0.5)) = 0x4B000000 + k (clamped for the
// d in (0,0.25) round-down case). Row stride 256 B; 0x4B000000*256 wraps to 0
// mod 2^32, so off = v*256 = k*256 exactly. k <= 64 (dump row).
__device__ __forceinline__ unsigned off_of(float d2) {
    float d = fsqrt_approx(d2);
    unsigned v = __float_as_uint(fminf(d, 64.0f) + 8388607.5f);
    v = max(v, 0x4B000000u);
    return v * 256u;
}

// ---------- kernel 1: pairwise histogram (byte-identical to R13) ----------
__global__ __launch_bounds__(TILE, 8) void hist_kernel(const float* __restrict__ pos) {
    __shared__ __align__(16) unsigned short sh_hist[HROWS * TILE];   // 16896 B
    __shared__ __align__(16) float xs[192], ys[192], zs[192];        // 192: mod-free diag
    __shared__ unsigned int red_u[TILE];

    const int t = threadIdx.x;
    const int g = blockIdx.y;

    int ti = 0, rem = blockIdx.x;
    while (rem >= NTILE - ti) { rem -= NTILE - ti; ++ti; }
    const int tj = ti + rem;

    {
        uint4* z = (uint4*)sh_hist;
        const uint4 zero = make_uint4(0, 0, 0, 0);
        #pragma unroll
        for (int i = t; i < HROWS * TILE * 2 / 16; i += TILE) z[i] = zero;
    }

    const float SCALE = 2.56f;   // NUM_BINS / MAX_DIST

    {
        const float* q = pos + ((size_t)(g * SPTS + tj * TILE + t)) * 3;
        float qx = q[0] * SCALE, qy = q[1] * SCALE, qz = q[2] * SCALE;
        xs[t] = qx; ys[t] = qy; zs[t] = qz;
        if (t < 64) { xs[128 + t] = qx; ys[128 + t] = qy; zs[128 + t] = qz; }
    }
    const float* r = pos + ((size_t)(g * SPTS + ti * TILE + t)) * 3;
    const float xi = r[0] * SCALE, yi = r[1] * SCALE, zi = r[2] * SCALE;

    __syncthreads();

    // bank-conflict-free per-thread slot within each 256B row
    char* hb = (char*)sh_hist + (4 * (t & 31) + 128 * ((t >> 5) & 1) + 2 * (t >> 6));

    if (ti != tj) {
        const ull nxi = f2_pack(-xi, -xi);
        const ull nyi = f2_pack(-yi, -yi);
        const ull nzi = f2_pack(-zi, -zi);
        const ull* X2 = (const ull*)xs;
        const ull* Y2 = (const ull*)ys;
        const ull* Z2 = (const ull*)zs;
        #pragma unroll 8
        for (int h = 0; h < TILE / 2; ++h) {
            ull dx = f2_add(X2[h], nxi);
            ull dy = f2_add(Y2[h], nyi);
            ull dz = f2_add(Z2[h], nzi);
            ull d2 = f2_fma(dx, dx, f2_fma(dy, dy, f2_mul(dz, dz)));
            float a, b; f2_unpack(d2, a, b);
            *(unsigned short*)(hb + off_of(a)) += 1;
            *(unsigned short*)(hb + off_of(b)) += 1;
        }
    } else {
        // diagonal: pairs (t, t+c) for c = 1..64; c = 64 counts only for t < 64
        const unsigned short incLast = (unsigned short)(t < 64 ? 1 : 0);
        #pragma unroll 8
        for (int c = 1; c <= 64; ++c) {
            const int j = t + c;
            float dx = xs[j] - xi;
            float dy = ys[j] - yi;
            float dz = zs[j] - zi;
            float d2 = fmaf(dx, dx, fmaf(dy, dy, dz * dz));
            unsigned short inc = (c < 64) ? (unsigned short)1 : incLast;
            *(unsigned short*)(hb + off_of(d2)) += inc;
        }
    }

    __syncthreads();

    {
        const unsigned int* H = (const unsigned int*)sh_hist;
        const int b   = t & 63;
        const int seg = t >> 6;
        unsigned s = 0;
        #pragma unroll 8
        for (int a = 0; a < 32; ++a) {
            unsigned w = H[b * 64 + seg * 32 + ((a + b) & 31)];
            s += (w & 0xFFFFu) + (w >> 16);
        }
        red_u[t] = s;
    }
    __syncthreads();
    if (t < NBINS) g_part[g][blockIdx.x][t] = red_u[t] + red_u[t + 64];
    __syncthreads();
    if (t == 0) {
        __threadfence();
        asm volatile("griddepcontrol.launch_dependents;");
    }
}

// ---------- kernel 2: MLP, 32-unit slices (32 KB smem -> co-resident with hist) ----------
// grid = (8 slices, 64 graphs), block = 128.
// Layer 2: 4 threads per unit (quarter K-dots into smem), then one thread per
// unit combines quarters in fixed order ((q0+q1)+(q2+q3)) -> deterministic.
__global__ __launch_bounds__(128) void mlp_kernel(const float* __restrict__ W1,
                                                  const float* __restrict__ b1,
                                                  const float* __restrict__ W2,
                                                  const float* __restrict__ b2,
                                                  float* __restrict__ out) {
    extern __shared__ __align__(16) float w2s[];          // 32 KB dynamic
    __shared__ float hn[NBINS];
    __shared__ __align__(16) float act[HIDDEN];
    __shared__ float qsum[4 * SLICE];
    __shared__ float inv_s;

    const int g = blockIdx.y;
    const int s = blockIdx.x;
    const int t = threadIdx.x;

    // 1. fire W2 slice loads (independent of histogram results)
    {
        const float* src_base = W2 + (size_t)(s * SLICE) * HIDDEN;
        const unsigned sbase = smem_u32(w2s);
        #pragma unroll
        for (int i = 0; i < 16; ++i) {
            int idx = t + 128 * i;                 // 0..2047 float4 chunks
            int u   = idx >> 6;                    // unit 0..31
            int k4  = idx & 63;                    // float4 slot 0..63
            const float* src = src_base + (size_t)u * HIDDEN + k4 * 4;
            unsigned dst = sbase + (unsigned)(u * 256 + (((k4 + u) & 63) << 2)) * 4u;
            asm volatile("cp.async.cg.shared.global [%0], [%1], 16;" :: "r"(dst), "l"(src));
        }
        asm volatile("cp.async.commit_group;");
    }

    // 2. wait for primary grid's g_part to be complete & visible
    asm volatile("griddepcontrol.wait;" ::: "memory");

    if (t < NBINS) {
        unsigned sum = 0;
        #pragma unroll
        for (int m = 0; m < NPAIRS; ++m) sum += g_part[g][m][t];
        hn[t] = (float)sum;
    }
    __syncthreads();

    // 3. total count via warp-0 shuffle reduction (fixed order -> deterministic)
    if (t < 32) {
        float v = hn[t] + hn[t + 32];
        v += __shfl_down_sync(0xffffffffu, v, 16);
        v += __shfl_down_sync(0xffffffffu, v, 8);
        v += __shfl_down_sync(0xffffffffu, v, 4);
        v += __shfl_down_sync(0xffffffffu, v, 2);
        v += __shfl_down_sync(0xffffffffu, v, 1);
        if (t == 0) inv_s = 1.0f / (v + 1e-8f);
    }
    __syncthreads();
    const float inv = inv_s;

    // 4. layer 1: silu(hist_norm @ W1.T + b1), 2 units per thread
    #pragma unroll
    for (int u = t; u < HIDDEN; u += 128) {
        const float4* w = reinterpret_cast<const float4*>(W1 + (size_t)u * NBINS);
        float dot = 0.0f;
        #pragma unroll
        for (int k = 0; k < NBINS / 4; ++k) {
            float4 ww = w[k];
            dot = fmaf(ww.x, hn[4*k+0], dot);
            dot = fmaf(ww.y, hn[4*k+1], dot);
            dot = fmaf(ww.z, hn[4*k+2], dot);
            dot = fmaf(ww.w, hn[4*k+3], dot);
        }
        float x   = fmaf(dot, inv, b1[u]);
        float sig = 1.0f / (1.0f + __expf(-x));
        act[u] = x * sig;
    }
    asm volatile("cp.async.wait_group 0;" ::: "memory");
    __syncthreads();

    // 5. layer 2, phase A: 4 threads per unit, each a quarter of K (64 elems)
    {
        const int u = t & 31;          // unit within slice
        const int q = t >> 5;          // quarter 0..3
        const float4* av = reinterpret_cast<const float4*>(act) + q * 16;
        float acc = 0.0f;
        #pragma unroll
        for (int kk = 0; kk < 16; ++kk) {
            const int k4 = q * 16 + kk;
            const float4 w = *reinterpret_cast<const float4*>(w2s + u * 256 + (((k4 + u) & 63) << 2));
            const float4 a = av[kk];
            acc = fmaf(w.x, a.x, acc);
            acc = fmaf(w.y, a.y, acc);
            acc = fmaf(w.z, a.z, acc);
            acc = fmaf(w.w, a.w, acc);
        }
        qsum[q * SLICE + u] = acc;
    }
    __syncthreads();

    // 5b. phase B: combine quarters in fixed order, add bias, store
    if (t < SLICE) {
        float r = (qsum[t] + qsum[SLICE + t]) + (qsum[2 * SLICE + t] + qsum[3 * SLICE + t]);
        out[(size_t)g * HIDDEN + s * SLICE + t] = r + b2[s * SLICE + t];
    }
}

extern "C" void kernel_launch(void* const* d_in, const int* in_sizes, int n_in,
                              void* d_out, int out_size) {
    // Size-based input ID: pos=196608, W1=16384, W2=first 65536 (batch i32 comes
    // later), b1/b2 = 256 in order.
    int iPos = 0, iW1 = 1, ib1 = 2, iW2 = 3, ib2 = 4;
    {
        int fp = -1, f1 = -1, f2v = -1, fb1 = -1, fb2 = -1;
        for (int i = 0; i < n_in; ++i) {
            int sz = in_sizes[i];
            if (sz == 196608 && fp < 0) fp = i;
            else if (sz == 16384 && f1 < 0) f1 = i;
            else if (sz == 65536 && f2v < 0) f2v = i;
            else if (sz == 256) { if (fb1 < 0) fb1 = i; else if (fb2 < 0) fb2 = i; }
        }
        if (fp >= 0 && f1 >= 0 && f2v >= 0 && fb1 >= 0 && fb2 >= 0) {
            iPos = fp; iW1 = f1; iW2 = f2v; ib1 = fb1; ib2 = fb2;
        }
    }
    const float* pos = (const float*)d_in[iPos];
    const float* W1  = (const float*)d_in[iW1];
    const float* b1  = (const float*)d_in[ib1];
    const float* W2  = (const float*)d_in[iW2];
    const float* b2  = (const float*)d_in[ib2];
    float* out = (float*)d_out;

    const int dyn = SLICE * HIDDEN * (int)sizeof(float);   // 32 KB
    static bool configured = false;
    if (!configured) {
        cudaFuncSetAttribute(mlp_kernel, cudaFuncAttributeMaxDynamicSharedMemorySize, dyn);
        configured = true;
    }

    hist_kernel<<<dim3(NPAIRS, NGRAPH), TILE>>>(pos);

    cudaLaunchConfig_t cfg = {};
    cfg.gridDim  = dim3(8, NGRAPH);
    cfg.blockDim = dim3(128);
    cfg.dynamicSmemBytes = dyn;
    cfg.stream = 0;
    cudaLaunchAttribute attrs[1];
    attrs[0].id = cudaLaunchAttributeProgrammaticStreamSerialization;
    attrs[0].val.programmaticStreamSerializationAllowed = 1;
    cfg.attrs = attrs;
    cfg.numAttrs = 1;
    cudaLaunchKernelEx(&cfg, mlp_kernel, W1, b1, W2, b2, out);
}

// round 15
// speedup vs baseline: 1.0642x; 1.0642x over previous
#include <cuda_runtime.h>

#define NGRAPH 64
#define SPTS   1024
#define TILE   128
#define NTILE  8
#define NPAIRS 36           // tile-pairs per graph (ti <= tj)
#define HIDDEN 256
#define NBINS  64
#define HROWS  66           // 64 bins + dump row + 1 pad row (uint4 init)
#define SLICE  64           // output units per mlp block
#define MLPTHREADS 256

typedef unsigned long long ull;

// per-(graph, tile-pair-block) partial histograms; fully overwritten every call
__device__ unsigned int g_part[NGRAPH][NPAIRS][NBINS];

// ---------- helpers ----------
__device__ __forceinline__ unsigned smem_u32(const void* p) {
    unsigned a;
    asm("{ .reg .u64 t; cvta.to.shared.u64 t, %1; cvt.u32.u64 %0, t; }" : "=r"(a) : "l"(p));
    return a;
}
__device__ __forceinline__ ull f2_pack(float a, float b) {
    ull r; asm("mov.b64 %0, {%1, %2};" : "=l"(r) : "f"(a), "f"(b)); return r;
}
__device__ __forceinline__ void f2_unpack(ull v, float& a, float& b) {
    asm("mov.b64 {%0, %1}, %2;" : "=f"(a), "=f"(b) : "l"(v));
}
__device__ __forceinline__ ull f2_add(ull a, ull b) {
    ull r; asm("add.rn.f32x2 %0, %1, %2;" : "=l"(r) : "l"(a), "l"(b)); return r;
}
__device__ __forceinline__ ull f2_mul(ull a, ull b) {
    ull r; asm("mul.rn.f32x2 %0, %1, %2;" : "=l"(r) : "l"(a), "l"(b)); return r;
}
__device__ __forceinline__ ull f2_fma(ull a, ull b, ull c) {
    ull r; asm("fma.rn.f32x2 %0, %1, %2, %3;" : "=l"(r) : "l"(a), "l"(b), "l"(c)); return r;
}
__device__ __forceinline__ float fsqrt_approx(float x) {
    float y; asm("sqrt.approx.f32 %0, %1;" : "=f"(y) : "f"(x)); return y;
}

// byte offset of the bin row for scaled squared distance d2.
// v = bits(fmin(sqrt(d2),64) + (2^23-0.5)) = 0x4B000000 + k (clamped for the
// d in (0,0.25) round-down case). Row stride 256 B; 0x4B000000*256 wraps to 0
// mod 2^32, so off = v*256 = k*256 exactly. k <= 64 (dump row).
__device__ __forceinline__ unsigned off_of(float d2) {
    float d = fsqrt_approx(d2);
    unsigned v = __float_as_uint(fminf(d, 64.0f) + 8388607.5f);
    v = max(v, 0x4B000000u);
    return v * 256u;
}

// ---------- kernel 1: pairwise histogram (byte-identical to R13) ----------
__global__ __launch_bounds__(TILE, 8) void hist_kernel(const float* __restrict__ pos) {
    __shared__ __align__(16) unsigned short sh_hist[HROWS * TILE];   // 16896 B
    __shared__ __align__(16) float xs[192], ys[192], zs[192];        // 192: mod-free diag
    __shared__ unsigned int red_u[TILE];

    const int t = threadIdx.x;
    const int g = blockIdx.y;

    int ti = 0, rem = blockIdx.x;
    while (rem >= NTILE - ti) { rem -= NTILE - ti; ++ti; }
    const int tj = ti + rem;

    {
        uint4* z = (uint4*)sh_hist;
        const uint4 zero = make_uint4(0, 0, 0, 0);
        #pragma unroll
        for (int i = t; i < HROWS * TILE * 2 / 16; i += TILE) z[i] = zero;
    }

    const float SCALE = 2.56f;   // NUM_BINS / MAX_DIST

    {
        const float* q = pos + ((size_t)(g * SPTS + tj * TILE + t)) * 3;
        float qx = q[0] * SCALE, qy = q[1] * SCALE, qz = q[2] * SCALE;
        xs[t] = qx; ys[t] = qy; zs[t] = qz;
        if (t < 64) { xs[128 + t] = qx; ys[128 + t] = qy; zs[128 + t] = qz; }
    }
    const float* r = pos + ((size_t)(g * SPTS + ti * TILE + t)) * 3;
    const float xi = r[0] * SCALE, yi = r[1] * SCALE, zi = r[2] * SCALE;

    __syncthreads();

    // bank-conflict-free per-thread slot within each 256B row
    char* hb = (char*)sh_hist + (4 * (t & 31) + 128 * ((t >> 5) & 1) + 2 * (t >> 6));

    if (ti != tj) {
        const ull nxi = f2_pack(-xi, -xi);
        const ull nyi = f2_pack(-yi, -yi);
        const ull nzi = f2_pack(-zi, -zi);
        const ull* X2 = (const ull*)xs;
        const ull* Y2 = (const ull*)ys;
        const ull* Z2 = (const ull*)zs;
        #pragma unroll 8
        for (int h = 0; h < TILE / 2; ++h) {
            ull dx = f2_add(X2[h], nxi);
            ull dy = f2_add(Y2[h], nyi);
            ull dz = f2_add(Z2[h], nzi);
            ull d2 = f2_fma(dx, dx, f2_fma(dy, dy, f2_mul(dz, dz)));
            float a, b; f2_unpack(d2, a, b);
            *(unsigned short*)(hb + off_of(a)) += 1;
            *(unsigned short*)(hb + off_of(b)) += 1;
        }
    } else {
        // diagonal: pairs (t, t+c) for c = 1..64; c = 64 counts only for t < 64
        const unsigned short incLast = (unsigned short)(t < 64 ? 1 : 0);
        #pragma unroll 8
        for (int c = 1; c <= 64; ++c) {
            const int j = t + c;
            float dx = xs[j] - xi;
            float dy = ys[j] - yi;
            float dz = zs[j] - zi;
            float d2 = fmaf(dx, dx, fmaf(dy, dy, dz * dz));
            unsigned short inc = (c < 64) ? (unsigned short)1 : incLast;
            *(unsigned short*)(hb + off_of(d2)) += inc;
        }
    }

    __syncthreads();

    {
        const unsigned int* H = (const unsigned int*)sh_hist;
        const int b   = t & 63;
        const int seg = t >> 6;
        unsigned s = 0;
        #pragma unroll 8
        for (int a = 0; a < 32; ++a) {
            unsigned w = H[b * 64 + seg * 32 + ((a + b) & 31)];
            s += (w & 0xFFFFu) + (w >> 16);
        }
        red_u[t] = s;
    }
    __syncthreads();
    if (t < NBINS) g_part[g][blockIdx.x][t] = red_u[t] + red_u[t + 64];
    __syncthreads();
    if (t == 0) {
        __threadfence();
        asm volatile("griddepcontrol.launch_dependents;");
    }
}

// ---------- kernel 2: MLP, 256 threads, 4 blocks/graph (shortened phase chain) ----------
// grid = (4 slices, 64 graphs), block = 256.
// Layer 1: 1 unit/thread. Layer 2: 4 threads/unit quarter-dots into qsum, then
// one thread per unit combines ((q0+q1)+(q2+q3)) -> deterministic.
__global__ __launch_bounds__(MLPTHREADS) void mlp_kernel(const float* __restrict__ W1,
                                                         const float* __restrict__ b1,
                                                         const float* __restrict__ W2,
                                                         const float* __restrict__ b2,
                                                         float* __restrict__ out) {
    extern __shared__ __align__(16) float w2s[];          // 64 KB dynamic
    __shared__ float hn[NBINS];
    __shared__ __align__(16) float act[HIDDEN];
    __shared__ float qsum[4 * SLICE];
    __shared__ float inv_s;

    const int g = blockIdx.y;
    const int s = blockIdx.x;
    const int t = threadIdx.x;

    // 1. fire W2 slice loads (independent of histogram results)
    {
        const float* src_base = W2 + (size_t)(s * SLICE) * HIDDEN;
        const unsigned sbase = smem_u32(w2s);
        #pragma unroll
        for (int i = 0; i < 16; ++i) {
            int idx = t + MLPTHREADS * i;          // 0..4095 float4 chunks
            int u   = idx >> 6;
            int k4  = idx & 63;
            const float* src = src_base + (size_t)u * HIDDEN + k4 * 4;
            unsigned dst = sbase + (unsigned)(u * 256 + (((k4 + u) & 63) << 2)) * 4u;
            asm volatile("cp.async.cg.shared.global [%0], [%1], 16;" :: "r"(dst), "l"(src));
        }
        asm volatile("cp.async.commit_group;");
    }

    // 2. wait for primary grid's g_part to be complete & visible
    asm volatile("griddepcontrol.wait;" ::: "memory");

    if (t < NBINS) {
        unsigned sum = 0;
        #pragma unroll
        for (int m = 0; m < NPAIRS; ++m) sum += g_part[g][m][t];
        hn[t] = (float)sum;
    }
    __syncthreads();

    // 3. total count via warp-0 shuffle reduction (fixed order -> deterministic)
    if (t < 32) {
        float v = hn[t] + hn[t + 32];
        v += __shfl_down_sync(0xffffffffu, v, 16);
        v += __shfl_down_sync(0xffffffffu, v, 8);
        v += __shfl_down_sync(0xffffffffu, v, 4);
        v += __shfl_down_sync(0xffffffffu, v, 2);
        v += __shfl_down_sync(0xffffffffu, v, 1);
        if (t == 0) inv_s = 1.0f / (v + 1e-8f);
    }
    __syncthreads();
    const float inv = inv_s;

    // 4. layer 1: silu(hist_norm @ W1.T + b1), 1 unit per thread
    {
        const int u = t;
        const float4* w = reinterpret_cast<const float4*>(W1 + (size_t)u * NBINS);
        float dot = 0.0f;
        #pragma unroll
        for (int k = 0; k < NBINS / 4; ++k) {
            float4 ww = w[k];
            dot = fmaf(ww.x, hn[4*k+0], dot);
            dot = fmaf(ww.y, hn[4*k+1], dot);
            dot = fmaf(ww.z, hn[4*k+2], dot);
            dot = fmaf(ww.w, hn[4*k+3], dot);
        }
        float x   = fmaf(dot, inv, b1[u]);
        float sig = 1.0f / (1.0f + __expf(-x));
        act[u] = x * sig;
    }
    asm volatile("cp.async.wait_group 0;" ::: "memory");
    __syncthreads();

    // 5. layer 2, phase A: 4 threads per unit, each a quarter of K (64 elems)
    {
        const int u = t & 63;          // unit within slice
        const int q = t >> 6;          // quarter 0..3
        const float4* av = reinterpret_cast<const float4*>(act) + q * 16;
        float acc = 0.0f;
        #pragma unroll
        for (int kk = 0; kk < 16; ++kk) {
            const int k4 = q * 16 + kk;
            const float4 w = *reinterpret_cast<const float4*>(w2s + u * 256 + (((k4 + u) & 63) << 2));
            const float4 a = av[kk];
            acc = fmaf(w.x, a.x, acc);
            acc = fmaf(w.y, a.y, acc);
            acc = fmaf(w.z, a.z, acc);
            acc = fmaf(w.w, a.w, acc);
        }
        qsum[q * SLICE + u] = acc;
    }
    __syncthreads();

    // 5b. phase B: combine quarters in fixed order, add bias, store
    if (t < SLICE) {
        float r = (qsum[t] + qsum[SLICE + t]) + (qsum[2 * SLICE + t] + qsum[3 * SLICE + t]);
        out[(size_t)g * HIDDEN + s * SLICE + t] = r + b2[s * SLICE + t];
    }
}

extern "C" void kernel_launch(void* const* d_in, const int* in_sizes, int n_in,
                              void* d_out, int out_size) {
    // Size-based input ID: pos=196608, W1=16384, W2=first 65536 (batch i32 comes
    // later), b1/b2 = 256 in order.
    int iPos = 0, iW1 = 1, ib1 = 2, iW2 = 3, ib2 = 4;
    {
        int fp = -1, f1 = -1, f2v = -1, fb1 = -1, fb2 = -1;
        for (int i = 0; i < n_in; ++i) {
            int sz = in_sizes[i];
            if (sz == 196608 && fp < 0) fp = i;
            else if (sz == 16384 && f1 < 0) f1 = i;
            else if (sz == 65536 && f2v < 0) f2v = i;
            else if (sz == 256) { if (fb1 < 0) fb1 = i; else if (fb2 < 0) fb2 = i; }
        }
        if (fp >= 0 && f1 >= 0 && f2v >= 0 && fb1 >= 0 && fb2 >= 0) {
            iPos = fp; iW1 = f1; iW2 = f2v; ib1 = fb1; ib2 = fb2;
        }
    }
    const float* pos = (const float*)d_in[iPos];
    const float* W1  = (const float*)d_in[iW1];
    const float* b1  = (const float*)d_in[ib1];
    const float* W2  = (const float*)d_in[iW2];
    const float* b2  = (const float*)d_in[ib2];
    float* out = (float*)d_out;

    const int dyn = SLICE * HIDDEN * (int)sizeof(float);   // 64 KB
    static bool configured = false;
    if (!configured) {
        cudaFuncSetAttribute(mlp_kernel, cudaFuncAttributeMaxDynamicSharedMemorySize, dyn);
        configured = true;
    }

    hist_kernel<<<dim3(NPAIRS, NGRAPH), TILE>>>(pos);

    cudaLaunchConfig_t cfg = {};
    cfg.gridDim  = dim3(4, NGRAPH);
    cfg.blockDim = dim3(MLPTHREADS);
    cfg.dynamicSmemBytes = dyn;
    cfg.stream = 0;
    cudaLaunchAttribute attrs[1];
    attrs[0].id = cudaLaunchAttributeProgrammaticStreamSerialization;
    attrs[0].val.programmaticStreamSerializationAllowed = 1;
    cfg.attrs = attrs;
    cfg.numAttrs = 1;
    cudaLaunchKernelEx(&cfg, mlp_kernel, W1, b1, W2, b2, out);
}

// round 16
// speedup vs baseline: 1.0971x; 1.0309x over previous
#include <cuda_runtime.h>

#define NGRAPH 64
#define SPTS   1024
#define TILE   128
#define NTILE  8
#define NPAIRS 36           // tile-pairs per graph (ti <= tj)
#define HIDDEN 256
#define NBINS  64
#define HROWS  65           // 64 bins + dump row (u8, 128 B rows)
#define SLICE  64           // output units per mlp block

typedef unsigned long long ull;

// per-(graph, tile-pair-block) partial histograms; fully overwritten every call
__device__ unsigned int g_part[NGRAPH][NPAIRS][NBINS];

// ---------- helpers ----------
__device__ __forceinline__ unsigned smem_u32(const void* p) {
    unsigned a;
    asm("{ .reg .u64 t; cvta.to.shared.u64 t, %1; cvt.u32.u64 %0, t; }" : "=r"(a) : "l"(p));
    return a;
}
__device__ __forceinline__ ull f2_pack(float a, float b) {
    ull r; asm("mov.b64 %0, {%1, %2};" : "=l"(r) : "f"(a), "f"(b)); return r;
}
__device__ __forceinline__ void f2_unpack(ull v, float& a, float& b) {
    asm("mov.b64 {%0, %1}, %2;" : "=f"(a), "=f"(b) : "l"(v));
}
__device__ __forceinline__ ull f2_add(ull a, ull b) {
    ull r; asm("add.rn.f32x2 %0, %1, %2;" : "=l"(r) : "l"(a), "l"(b)); return r;
}
__device__ __forceinline__ ull f2_mul(ull a, ull b) {
    ull r; asm("mul.rn.f32x2 %0, %1, %2;" : "=l"(r) : "l"(a), "l"(b)); return r;
}
__device__ __forceinline__ ull f2_fma(ull a, ull b, ull c) {
    ull r; asm("fma.rn.f32x2 %0, %1, %2, %3;" : "=l"(r) : "l"(a), "l"(b), "l"(c)); return r;
}
__device__ __forceinline__ float fsqrt_approx(float x) {
    float y; asm("sqrt.approx.f32 %0, %1;" : "=f"(y) : "f"(x)); return y;
}

// byte offset of the bin row (u8 counters, 128 B per row) for scaled d2.
// v = bits(fmin(sqrt(d2),64) + (2^23-0.5)) = 0x4B000000 + k (clamped for the
// d in (0,0.25) round-down case). v*128 mod 2^32 = k*128 + 0x80000000, so
// adding 0x80000000u cancels the residue: off = k*128 exactly. k <= 64.
__device__ __forceinline__ unsigned off_of(float d2) {
    float d = fsqrt_approx(d2);
    unsigned v = __float_as_uint(fminf(d, 64.0f) + 8388607.5f);
    v = max(v, 0x4B000000u);
    return v * 128u + 0x80000000u;
}

// ---------- kernel 1: pairwise histogram (R13 structure, u8 counters) ----------
// grid = (36 tile-pairs, 64 graphs), block = 128 threads.
// Per-thread u8 slot: word index (t&31) within the row (32 distinct banks per
// warp), byte lane (t>>5). Max pairs/thread/block = 128 < 256 -> u8 exact.
__global__ __launch_bounds__(TILE, 8) void hist_kernel(const float* __restrict__ pos) {
    __shared__ __align__(16) unsigned char sh_hist[HROWS * 128];     // 8320 B
    __shared__ __align__(16) float xs[192], ys[192], zs[192];        // 192: mod-free diag
    __shared__ unsigned int red_u[TILE];

    const int t = threadIdx.x;
    const int g = blockIdx.y;

    int ti = 0, rem = blockIdx.x;
    while (rem >= NTILE - ti) { rem -= NTILE - ti; ++ti; }
    const int tj = ti + rem;

    // uint4 zero-init: 8320 B = 520 uint4
    {
        uint4* z = (uint4*)sh_hist;
        const uint4 zero = make_uint4(0, 0, 0, 0);
        #pragma unroll
        for (int i = t; i < HROWS * 128 / 16; i += TILE) z[i] = zero;
    }

    const float SCALE = 2.56f;   // NUM_BINS / MAX_DIST

    {
        const float* q = pos + ((size_t)(g * SPTS + tj * TILE + t)) * 3;
        float qx = q[0] * SCALE, qy = q[1] * SCALE, qz = q[2] * SCALE;
        xs[t] = qx; ys[t] = qy; zs[t] = qz;
        if (t < 64) { xs[128 + t] = qx; ys[128 + t] = qy; zs[128 + t] = qz; }
    }
    const float* r = pos + ((size_t)(g * SPTS + ti * TILE + t)) * 3;
    const float xi = r[0] * SCALE, yi = r[1] * SCALE, zi = r[2] * SCALE;

    __syncthreads();

    // per-thread u8 slot: 32 distinct banks per warp, byte lane per warp
    char* hb = (char*)sh_hist + (4 * (t & 31) + (t >> 5));

    if (ti != tj) {
        const ull nxi = f2_pack(-xi, -xi);
        const ull nyi = f2_pack(-yi, -yi);
        const ull nzi = f2_pack(-zi, -zi);
        const ull* X2 = (const ull*)xs;
        const ull* Y2 = (const ull*)ys;
        const ull* Z2 = (const ull*)zs;
        #pragma unroll 8
        for (int h = 0; h < TILE / 2; ++h) {
            ull dx = f2_add(X2[h], nxi);
            ull dy = f2_add(Y2[h], nyi);
            ull dz = f2_add(Z2[h], nzi);
            ull d2 = f2_fma(dx, dx, f2_fma(dy, dy, f2_mul(dz, dz)));
            float a, b; f2_unpack(d2, a, b);
            *(unsigned char*)(hb + off_of(a)) += 1;
            *(unsigned char*)(hb + off_of(b)) += 1;
        }
    } else {
        // diagonal: pairs (t, t+c) for c = 1..64; c = 64 counts only for t < 64
        const unsigned char incLast = (unsigned char)(t < 64 ? 1 : 0);
        #pragma unroll 8
        for (int c = 1; c <= 64; ++c) {
            const int j = t + c;
            float dx = xs[j] - xi;
            float dy = ys[j] - yi;
            float dz = zs[j] - zi;
            float d2 = fmaf(dx, dx, fmaf(dy, dy, dz * dz));
            unsigned char inc = (c < 64) ? (unsigned char)1 : incLast;
            *(unsigned char*)(hb + off_of(d2)) += inc;
        }
    }

    __syncthreads();

    // reduce: each bin row = 32 words x 4 byte-counters; dp4a sums 4 at once.
    // 2 threads per bin (seg 0/1), 16 words each, rotated by bin.
    {
        const unsigned int* H = (const unsigned int*)sh_hist;
        const int b   = t & 63;
        const int seg = t >> 6;
        unsigned s = 0;
        #pragma unroll
        for (int a = 0; a < 16; ++a) {
            unsigned w = H[b * 32 + seg * 16 + ((a + b) & 15)];
            s = __dp4a(w, 0x01010101u, s);
        }
        red_u[t] = s;
    }
    __syncthreads();
    if (t < NBINS) g_part[g][blockIdx.x][t] = red_u[t] + red_u[t + 64];
    __syncthreads();
    if (t == 0) {
        __threadfence();
        asm volatile("griddepcontrol.launch_dependents;");
    }
}

// ---------- kernel 2: MLP (byte-identical to R13, measured-best) ----------
__global__ __launch_bounds__(128) void mlp_kernel(const float* __restrict__ W1,
                                                  const float* __restrict__ b1,
                                                  const float* __restrict__ W2,
                                                  const float* __restrict__ b2,
                                                  float* __restrict__ out) {
    extern __shared__ __align__(16) float w2s[];          // 64 KB dynamic
    __shared__ float hn[NBINS];
    __shared__ __align__(16) float act[HIDDEN];
    __shared__ float inv_s;

    const int g = blockIdx.y;
    const int s = blockIdx.x;
    const int t = threadIdx.x;

    // 1. fire W2 slice loads (independent of histogram results)
    {
        const float* src_base = W2 + (size_t)(s * SLICE) * HIDDEN;
        const unsigned sbase = smem_u32(w2s);
        #pragma unroll
        for (int i = 0; i < 32; ++i) {
            int idx = t + 128 * i;                 // 0..4095 float4 chunks
            int u   = idx >> 6;
            int k4  = idx & 63;
            const float* src = src_base + (size_t)u * HIDDEN + k4 * 4;
            unsigned dst = sbase + (unsigned)(u * 256 + (((k4 + u) & 63) << 2)) * 4u;
            asm volatile("cp.async.cg.shared.global [%0], [%1], 16;" :: "r"(dst), "l"(src));
        }
        asm volatile("cp.async.commit_group;");
    }

    // 2. wait for primary grid's g_part to be complete & visible
    asm volatile("griddepcontrol.wait;" ::: "memory");

    if (t < NBINS) {
        unsigned sum = 0;
        #pragma unroll
        for (int m = 0; m < NPAIRS; ++m) sum += g_part[g][m][t];
        hn[t] = (float)sum;
    }
    __syncthreads();

    // 3. total count via warp-0 shuffle reduction (fixed order -> deterministic)
    if (t < 32) {
        float v = hn[t] + hn[t + 32];
        v += __shfl_down_sync(0xffffffffu, v, 16);
        v += __shfl_down_sync(0xffffffffu, v, 8);
        v += __shfl_down_sync(0xffffffffu, v, 4);
        v += __shfl_down_sync(0xffffffffu, v, 2);
        v += __shfl_down_sync(0xffffffffu, v, 1);
        if (t == 0) inv_s = 1.0f / (v + 1e-8f);
    }
    __syncthreads();
    const float inv = inv_s;

    // 4. layer 1: silu(hist_norm @ W1.T + b1), 2 units per thread
    #pragma unroll
    for (int u = t; u < HIDDEN; u += 128) {
        const float4* w = reinterpret_cast<const float4*>(W1 + (size_t)u * NBINS);
        float dot = 0.0f;
        #pragma unroll
        for (int k = 0; k < NBINS / 4; ++k) {
            float4 ww = w[k];
            dot = fmaf(ww.x, hn[4*k+0], dot);
            dot = fmaf(ww.y, hn[4*k+1], dot);
            dot = fmaf(ww.z, hn[4*k+2], dot);
            dot = fmaf(ww.w, hn[4*k+3], dot);
        }
        float x   = fmaf(dot, inv, b1[u]);
        float sig = 1.0f / (1.0f + __expf(-x));
        act[u] = x * sig;
    }
    asm volatile("cp.async.wait_group 0;" ::: "memory");
    __syncthreads();

    // 5. layer 2: one thread per unit, all-smem FMA, diagonal-swizzled reads
    if (t < SLICE) {
        const int u = t;
        const float4* av = reinterpret_cast<const float4*>(act);
        float acc = b2[s * SLICE + u];
        #pragma unroll 8
        for (int k = 0; k < 64; ++k) {
            const float4 w = *reinterpret_cast<const float4*>(w2s + u * 256 + (((k + u) & 63) << 2));
            const float4 a = av[k];
            acc = fmaf(w.x, a.x, acc);
            acc = fmaf(w.y, a.y, acc);
            acc = fmaf(w.z, a.z, acc);
            acc = fmaf(w.w, a.w, acc);
        }
        out[(size_t)g * HIDDEN + s * SLICE + u] = acc;
    }
}

extern "C" void kernel_launch(void* const* d_in, const int* in_sizes, int n_in,
                              void* d_out, int out_size) {
    // Size-based input ID: pos=196608, W1=16384, W2=first 65536 (batch i32 comes
    // later), b1/b2 = 256 in order.
    int iPos = 0, iW1 = 1, ib1 = 2, iW2 = 3, ib2 = 4;
    {
        int fp = -1, f1 = -1, f2v = -1, fb1 = -1, fb2 = -1;
        for (int i = 0; i < n_in; ++i) {
            int sz = in_sizes[i];
            if (sz == 196608 && fp < 0) fp = i;
            else if (sz == 16384 && f1 < 0) f1 = i;
            else if (sz == 65536 && f2v < 0) f2v = i;
            else if (sz == 256) { if (fb1 < 0) fb1 = i; else if (fb2 < 0) fb2 = i; }
        }
        if (fp >= 0 && f1 >= 0 && f2v >= 0 && fb1 >= 0 && fb2 >= 0) {
            iPos = fp; iW1 = f1; iW2 = f2v; ib1 = fb1; ib2 = fb2;
        }
    }
    const float* pos = (const float*)d_in[iPos];
    const float* W1  = (const float*)d_in[iW1];
    const float* b1  = (const float*)d_in[ib1];
    const float* W2  = (const float*)d_in[iW2];
    const float* b2  = (const float*)d_in[ib2];
    float* out = (float*)d_out;

    const int dyn = SLICE * HIDDEN * (int)sizeof(float);   // 64 KB
    static bool configured = false;
    if (!configured) {
        cudaFuncSetAttribute(mlp_kernel, cudaFuncAttributeMaxDynamicSharedMemorySize, dyn);
        configured = true;
    }

    hist_kernel<<<dim3(NPAIRS, NGRAPH), TILE>>>(pos);

    cudaLaunchConfig_t cfg = {};
    cfg.gridDim  = dim3(4, NGRAPH);
    cfg.blockDim = dim3(128);
    cfg.dynamicSmemBytes = dyn;
    cfg.stream = 0;
    cudaLaunchAttribute attrs[1];
    attrs[0].id = cudaLaunchAttributeProgrammaticStreamSerialization;
    attrs[0].val.programmaticStreamSerializationAllowed = 1;
    cfg.attrs = attrs;
    cfg.numAttrs = 1;
    cudaLaunchKernelEx(&cfg, mlp_kernel, W1, b1, W2, b2, out);
}

// round 17
// speedup vs baseline: 1.1037x; 1.0061x over previous
#include <cuda_runtime.h>

#define NGRAPH 64
#define SPTS   1024
#define TILE   128
#define NTILE  8
#define NPAIRS 36           // tile-pairs per graph (ti <= tj)
#define HIDDEN 256
#define NBINS  64
#define HROWS  65           // 64 bins + dump row (u8, 128 B rows)
#define SLICE  64           // output units per mlp block

typedef unsigned long long ull;

// per-(graph, tile-pair-block) partial histograms; fully overwritten every call
__device__ unsigned int g_part[NGRAPH][NPAIRS][NBINS];

// ---------- helpers ----------
__device__ __forceinline__ unsigned smem_u32(const void* p) {
    unsigned a;
    asm("{ .reg .u64 t; cvta.to.shared.u64 t, %1; cvt.u32.u64 %0, t; }" : "=r"(a) : "l"(p));
    return a;
}
__device__ __forceinline__ ull f2_pack(float a, float b) {
    ull r; asm("mov.b64 %0, {%1, %2};" : "=l"(r) : "f"(a), "f"(b)); return r;
}
__device__ __forceinline__ void f2_unpack(ull v, float& a, float& b) {
    asm("mov.b64 {%0, %1}, %2;" : "=f"(a), "=f"(b) : "l"(v));
}
__device__ __forceinline__ ull f2_add(ull a, ull b) {
    ull r; asm("add.rn.f32x2 %0, %1, %2;" : "=l"(r) : "l"(a), "l"(b)); return r;
}
__device__ __forceinline__ ull f2_mul(ull a, ull b) {
    ull r; asm("mul.rn.f32x2 %0, %1, %2;" : "=l"(r) : "l"(a), "l"(b)); return r;
}
__device__ __forceinline__ ull f2_fma(ull a, ull b, ull c) {
    ull r; asm("fma.rn.f32x2 %0, %1, %2, %3;" : "=l"(r) : "l"(a), "l"(b), "l"(c)); return r;
}
__device__ __forceinline__ float fsqrt_approx(float x) {
    float y; asm("sqrt.approx.f32 %0, %1;" : "=f"(y) : "f"(x)); return y;
}

// byte offset of the bin row (u8 counters, 128 B per row) for scaled d2.
// v = bits(fmin(sqrt(d2),64) + (2^23-0.5)) = 0x4B000000 + k (clamped for the
// d in (0,0.25) round-down case). v*128 mod 2^32 = k*128 + 0x80000000, so
// adding 0x80000000u cancels the residue: off = k*128 exactly. k <= 64.
__device__ __forceinline__ unsigned off_of(float d2) {
    float d = fsqrt_approx(d2);
    unsigned v = __float_as_uint(fminf(d, 64.0f) + 8388607.5f);
    v = max(v, 0x4B000000u);
    return v * 128u + 0x80000000u;
}

// ---------- kernel 1: pairwise histogram (u8 counters, LDS.128 geometry) ----------
// grid = (36 tile-pairs, 64 graphs), block = 128 threads.
// Off-diagonal inner loop loads 4 columns per 16B broadcast (ulonglong2 =
// LDS.128, 1 wavefront) feeding two f32x2 pipelines: smem wavefronts drop
// from 3.5/pair to 2.75/pair. Per-thread u8 slot: word (t&31), byte (t>>5).
__global__ __launch_bounds__(TILE, 8) void hist_kernel(const float* __restrict__ pos) {
    __shared__ __align__(16) unsigned char sh_hist[HROWS * 128];     // 8320 B
    __shared__ __align__(16) float xs[192], ys[192], zs[192];        // 192: mod-free diag
    __shared__ unsigned int red_u[TILE];

    const int t = threadIdx.x;
    const int g = blockIdx.y;

    int ti = 0, rem = blockIdx.x;
    while (rem >= NTILE - ti) { rem -= NTILE - ti; ++ti; }
    const int tj = ti + rem;

    // uint4 zero-init: 8320 B = 520 uint4
    {
        uint4* z = (uint4*)sh_hist;
        const uint4 zero = make_uint4(0, 0, 0, 0);
        #pragma unroll
        for (int i = t; i < HROWS * 128 / 16; i += TILE) z[i] = zero;
    }

    const float SCALE = 2.56f;   // NUM_BINS / MAX_DIST

    {
        const float* q = pos + ((size_t)(g * SPTS + tj * TILE + t)) * 3;
        float qx = q[0] * SCALE, qy = q[1] * SCALE, qz = q[2] * SCALE;
        xs[t] = qx; ys[t] = qy; zs[t] = qz;
        if (t < 64) { xs[128 + t] = qx; ys[128 + t] = qy; zs[128 + t] = qz; }
    }
    const float* r = pos + ((size_t)(g * SPTS + ti * TILE + t)) * 3;
    const float xi = r[0] * SCALE, yi = r[1] * SCALE, zi = r[2] * SCALE;

    __syncthreads();

    // per-thread u8 slot: 32 distinct banks per warp, byte lane per warp
    char* hb = (char*)sh_hist + (4 * (t & 31) + (t >> 5));

    if (ti != tj) {
        const ull nxi = f2_pack(-xi, -xi);
        const ull nyi = f2_pack(-yi, -yi);
        const ull nzi = f2_pack(-zi, -zi);
        const ulonglong2* X4 = (const ulonglong2*)xs;
        const ulonglong2* Y4 = (const ulonglong2*)ys;
        const ulonglong2* Z4 = (const ulonglong2*)zs;
        #pragma unroll 4
        for (int h = 0; h < TILE / 4; ++h) {
            const ulonglong2 X = X4[h];    // 4 columns per 16B broadcast load
            const ulonglong2 Y = Y4[h];
            const ulonglong2 Z = Z4[h];
            {
                ull dx = f2_add(X.x, nxi);
                ull dy = f2_add(Y.x, nyi);
                ull dz = f2_add(Z.x, nzi);
                ull d2 = f2_fma(dx, dx, f2_fma(dy, dy, f2_mul(dz, dz)));
                float a, b; f2_unpack(d2, a, b);
                *(unsigned char*)(hb + off_of(a)) += 1;
                *(unsigned char*)(hb + off_of(b)) += 1;
            }
            {
                ull dx = f2_add(X.y, nxi);
                ull dy = f2_add(Y.y, nyi);
                ull dz = f2_add(Z.y, nzi);
                ull d2 = f2_fma(dx, dx, f2_fma(dy, dy, f2_mul(dz, dz)));
                float a, b; f2_unpack(d2, a, b);
                *(unsigned char*)(hb + off_of(a)) += 1;
                *(unsigned char*)(hb + off_of(b)) += 1;
            }
        }
    } else {
        // diagonal: pairs (t, t+c) for c = 1..64; c = 64 counts only for t < 64
        const unsigned char incLast = (unsigned char)(t < 64 ? 1 : 0);
        #pragma unroll 8
        for (int c = 1; c <= 64; ++c) {
            const int j = t + c;
            float dx = xs[j] - xi;
            float dy = ys[j] - yi;
            float dz = zs[j] - zi;
            float d2 = fmaf(dx, dx, fmaf(dy, dy, dz * dz));
            unsigned char inc = (c < 64) ? (unsigned char)1 : incLast;
            *(unsigned char*)(hb + off_of(d2)) += inc;
        }
    }

    __syncthreads();

    // reduce: each bin row = 32 words x 4 byte-counters; dp4a sums 4 at once.
    {
        const unsigned int* H = (const unsigned int*)sh_hist;
        const int b   = t & 63;
        const int seg = t >> 6;
        unsigned s = 0;
        #pragma unroll
        for (int a = 0; a < 16; ++a) {
            unsigned w = H[b * 32 + seg * 16 + ((a + b) & 15)];
            s = __dp4a(w, 0x01010101u, s);
        }
        red_u[t] = s;
    }
    __syncthreads();
    if (t < NBINS) g_part[g][blockIdx.x][t] = red_u[t] + red_u[t + 64];
    __syncthreads();
    if (t == 0) {
        __threadfence();
        asm volatile("griddepcontrol.launch_dependents;");
    }
}

// ---------- kernel 2: MLP (byte-identical to R13/R16, measured-best) ----------
__global__ __launch_bounds__(128) void mlp_kernel(const float* __restrict__ W1,
                                                  const float* __restrict__ b1,
                                                  const float* __restrict__ W2,
                                                  const float* __restrict__ b2,
                                                  float* __restrict__ out) {
    extern __shared__ __align__(16) float w2s[];          // 64 KB dynamic
    __shared__ float hn[NBINS];
    __shared__ __align__(16) float act[HIDDEN];
    __shared__ float inv_s;

    const int g = blockIdx.y;
    const int s = blockIdx.x;
    const int t = threadIdx.x;

    // 1. fire W2 slice loads (independent of histogram results)
    {
        const float* src_base = W2 + (size_t)(s * SLICE) * HIDDEN;
        const unsigned sbase = smem_u32(w2s);
        #pragma unroll
        for (int i = 0; i < 32; ++i) {
            int idx = t + 128 * i;                 // 0..4095 float4 chunks
            int u   = idx >> 6;
            int k4  = idx & 63;
            const float* src = src_base + (size_t)u * HIDDEN + k4 * 4;
            unsigned dst = sbase + (unsigned)(u * 256 + (((k4 + u) & 63) << 2)) * 4u;
            asm volatile("cp.async.cg.shared.global [%0], [%1], 16;" :: "r"(dst), "l"(src));
        }
        asm volatile("cp.async.commit_group;");
    }

    // 2. wait for primary grid's g_part to be complete & visible
    asm volatile("griddepcontrol.wait;" ::: "memory");

    if (t < NBINS) {
        unsigned sum = 0;
        #pragma unroll
        for (int m = 0; m < NPAIRS; ++m) sum += g_part[g][m][t];
        hn[t] = (float)sum;
    }
    __syncthreads();

    // 3. total count via warp-0 shuffle reduction (fixed order -> deterministic)
    if (t < 32) {
        float v = hn[t] + hn[t + 32];
        v += __shfl_down_sync(0xffffffffu, v, 16);
        v += __shfl_down_sync(0xffffffffu, v, 8);
        v += __shfl_down_sync(0xffffffffu, v, 4);
        v += __shfl_down_sync(0xffffffffu, v, 2);
        v += __shfl_down_sync(0xffffffffu, v, 1);
        if (t == 0) inv_s = 1.0f / (v + 1e-8f);
    }
    __syncthreads();
    const float inv = inv_s;

    // 4. layer 1: silu(hist_norm @ W1.T + b1), 2 units per thread
    #pragma unroll
    for (int u = t; u < HIDDEN; u += 128) {
        const float4* w = reinterpret_cast<const float4*>(W1 + (size_t)u * NBINS);
        float dot = 0.0f;
        #pragma unroll
        for (int k = 0; k < NBINS / 4; ++k) {
            float4 ww = w[k];
            dot = fmaf(ww.x, hn[4*k+0], dot);
            dot = fmaf(ww.y, hn[4*k+1], dot);
            dot = fmaf(ww.z, hn[4*k+2], dot);
            dot = fmaf(ww.w, hn[4*k+3], dot);
        }
        float x   = fmaf(dot, inv, b1[u]);
        float sig = 1.0f / (1.0f + __expf(-x));
        act[u] = x * sig;
    }
    asm volatile("cp.async.wait_group 0;" ::: "memory");
    __syncthreads();

    // 5. layer 2: one thread per unit, all-smem FMA, diagonal-swizzled reads
    if (t < SLICE) {
        const int u = t;
        const float4* av = reinterpret_cast<const float4*>(act);
        float acc = b2[s * SLICE + u];
        #pragma unroll 8
        for (int k = 0; k < 64; ++k) {
            const float4 w = *reinterpret_cast<const float4*>(w2s + u * 256 + (((k + u) & 63) << 2));
            const float4 a = av[k];
            acc = fmaf(w.x, a.x, acc);
            acc = fmaf(w.y, a.y, acc);
            acc = fmaf(w.z, a.z, acc);
            acc = fmaf(w.w, a.w, acc);
        }
        out[(size_t)g * HIDDEN + s * SLICE + u] = acc;
    }
}

extern "C" void kernel_launch(void* const* d_in, const int* in_sizes, int n_in,
                              void* d_out, int out_size) {
    // Size-based input ID: pos=196608, W1=16384, W2=first 65536 (batch i32 comes
    // later), b1/b2 = 256 in order.
    int iPos = 0, iW1 = 1, ib1 = 2, iW2 = 3, ib2 = 4;
    {
        int fp = -1, f1 = -1, f2v = -1, fb1 = -1, fb2 = -1;
        for (int i = 0; i < n_in; ++i) {
            int sz = in_sizes[i];
            if (sz == 196608 && fp < 0) fp = i;
            else if (sz == 16384 && f1 < 0) f1 = i;
            else if (sz == 65536 && f2v < 0) f2v = i;
            else if (sz == 256) { if (fb1 < 0) fb1 = i; else if (fb2 < 0) fb2 = i; }
        }
        if (fp >= 0 && f1 >= 0 && f2v >= 0 && fb1 >= 0 && fb2 >= 0) {
            iPos = fp; iW1 = f1; iW2 = f2v; ib1 = fb1; ib2 = fb2;
        }
    }
    const float* pos = (const float*)d_in[iPos];
    const float* W1  = (const float*)d_in[iW1];
    const float* b1  = (const float*)d_in[ib1];
    const float* W2  = (const float*)d_in[iW2];
    const float* b2  = (const float*)d_in[ib2];
    float* out = (float*)d_out;

    const int dyn = SLICE * HIDDEN * (int)sizeof(float);   // 64 KB
    static bool configured = false;
    if (!configured) {
        cudaFuncSetAttribute(mlp_kernel, cudaFuncAttributeMaxDynamicSharedMemorySize, dyn);
        configured = true;
    }

    hist_kernel<<<dim3(NPAIRS, NGRAPH), TILE>>>(pos);

    cudaLaunchConfig_t cfg = {};
    cfg.gridDim  = dim3(4, NGRAPH);
    cfg.blockDim = dim3(128);
    cfg.dynamicSmemBytes = dyn;
    cfg.stream = 0;
    cudaLaunchAttribute attrs[1];
    attrs[0].id = cudaLaunchAttributeProgrammaticStreamSerialization;
    attrs[0].val.programmaticStreamSerializationAllowed = 1;
    cfg.attrs = attrs;
    cfg.numAttrs = 1;
    cudaLaunchKernelEx(&cfg, mlp_kernel, W1, b1, W2, b2, out);
}